// round 8
// baseline (speedup 1.0000x reference)
#include <cuda_runtime.h>

#define LW 512
#define LH 512
#define NIMG 12
#define RAD 8
#define HW 2048

// Low-res {A, b} interleaved — only intermediate that touches HBM (24 MB).
__device__ float2 g_AB[(size_t)NIMG * LH * LW];

// ---------------------------------------------------------------------------
// Kernel 1 (fused stats) — round-4 version VERBATIM (passed twice, ~30us).
// Tile = 64 out-cols x 16 out-rows. Grid = 8 x 32 x 12 = 3072 blocks, 128 thr.
// ---------------------------------------------------------------------------
#define TC 64                 // out cols per tile
#define TR 16                 // out rows per tile
#define VC (TC + 2 * RAD)     // 80 loaded cols
#define VW 89                 // padded V row width (vpad(79)=88 -> 89)
#define STH 128

__device__ __forceinline__ int vpad(int v) { return v + (v >> 3); }

__global__ __launch_bounds__(STH) void stats_kernel(const float* __restrict__ lrx,
                                                    const float* __restrict__ lry) {
    __shared__ float4 Vsh[TR][VW];              // 22.8 KB vertical window sums
    __shared__ float2 ABsh[TR][TC];             // 8 KB
    __shared__ float2 ring[2 * RAD + 1][VC];    // 10.9 KB raw-row ring {x,y}

    int img = blockIdx.z;
    int cb  = blockIdx.x * TC;
    int r0  = blockIdx.y * TR;
    int t   = threadIdx.x;

    const float* xim = lrx + (size_t)img * LH * LW;
    const float* yim = lry + (size_t)img * LH * LW;

    // ---------------- phase 1: vertical sliding windows -------------------
    if (t < VC) {
        int gcol = cb - RAD + t;                // may be <0 or >=LW at edges
        bool cok = (gcol >= 0 && gcol < LW);
        float sx = 0.f, sy = 0.f, sxy = 0.f, sxx = 0.f;

        // init: rows r0-8 .. r0+8 (rows <0 contribute zero; r0+8 < LH always)
        for (int rr = r0 - RAD; rr <= r0 + RAD; ++rr) {
            float xv = 0.f, yv = 0.f;
            if (cok && rr >= 0) {
                xv = __ldg(xim + (size_t)rr * LW + gcol);
                yv = __ldg(yim + (size_t)rr * LW + gcol);
            }
            ring[(rr + 17) % 17][t] = make_float2(xv, yv);
            sx += xv; sy += yv; sxy += xv * yv; sxx += xv * xv;
        }

        for (int i = 0; i < TR; ++i) {
            Vsh[i][vpad(t)] = make_float4(sx, sy, sxy, sxx);

            int rsub = r0 + i - RAD;
            int radd = r0 + i + RAD + 1;        // radd - rsub = 17: same slot
            if (rsub >= 0) {
                float2 o = ring[(rsub + 17) % 17][t];  // read old FIRST
                sx -= o.x; sy -= o.y; sxy -= o.x * o.y; sxx -= o.x * o.x;
            }
            float xv = 0.f, yv = 0.f;
            if (cok && radd < LH) {
                xv = __ldg(xim + (size_t)radd * LW + gcol);
                yv = __ldg(yim + (size_t)radd * LW + gcol);
            }
            ring[radd % 17][t] = make_float2(xv, yv);
            sx += xv; sy += yv; sxy += xv * yv; sxx += xv * xv;
        }
    }
    __syncthreads();

    // ---------------- phase 2: horizontal sliding + A,b -------------------
    {
        int i   = t >> 3;          // row in tile, 0..15
        int seg = t & 7;           // 8-px segment, 0..7
        int c0  = seg * 8;
        int r   = r0 + i;

        int ylo = r - RAD; if (ylo < 0) ylo = 0;
        int yhi = r + RAD; if (yhi > LH - 1) yhi = LH - 1;
        float ny = (float)(yhi - ylo + 1);

        float sx = 0.f, sy = 0.f, sxy = 0.f, sxx = 0.f;
#pragma unroll
        for (int v = c0; v <= c0 + 2 * RAD; ++v) {
            float4 w = Vsh[i][vpad(v)];
            sx += w.x; sy += w.y; sxy += w.z; sxx += w.w;
        }
#pragma unroll
        for (int k = 0; k < 8; ++k) {
            int c  = c0 + k;
            int gc = cb + c;
            int xlo = gc - RAD; if (xlo < 0) xlo = 0;
            int xhi = gc + RAD; if (xhi > LW - 1) xhi = LW - 1;
            float invN = 1.0f / ((float)(xhi - xlo + 1) * ny);

            float mx  = sx  * invN;
            float my  = sy  * invN;
            float cov = sxy * invN - mx * my;
            float var = sxx * invN - mx * mx;
            float A   = cov / (var + 1e-8f);
            ABsh[i][c] = make_float2(A, my - A * mx);

            if (k < 7) {
                float4 a = Vsh[i][vpad(c + 2 * RAD + 1)];
                float4 s = Vsh[i][vpad(c)];
                sx += a.x - s.x; sy += a.y - s.y;
                sxy += a.z - s.z; sxx += a.w - s.w;
            }
        }
    }
    __syncthreads();

    // ---------------- coalesced output write ------------------------------
    size_t abase = (size_t)img * LH * LW;
    for (int idx = t; idx < TR * TC; idx += STH) {
        int i = idx >> 6;
        int c = idx & 63;
        g_AB[abase + (size_t)(r0 + i) * LW + cb + c] = ABsh[i][c];
    }
}

// ---------------------------------------------------------------------------
// Kernel 2: fused bilinear upsample, round-4 per-pixel math, 4 output rows
// per block: one setup+sync amortized over 64 KB of streaming.
// ---------------------------------------------------------------------------
#define UPTHREADS 256
#define UROWS 4

__global__ __launch_bounds__(UPTHREADS) void upsample_kernel(
        const float* __restrict__ hrx, float* __restrict__ out) {
    int bid  = blockIdx.x;
    int img  = bid >> 9;                 // 512 row-groups per image
    int oyb  = (bid & 511) * UROWS;
    int t    = threadIdx.x;

    const float SC = 511.0f / 2047.0f;

    __shared__ float2 sAB[UROWS][LW];    // y-interpolated {A,b}, 16 KB

#pragma unroll
    for (int rr = 0; rr < UROWS; ++rr) {
        int oy = oyb + rr;
        float yf = (float)oy * SC;
        int y0 = (int)yf; if (y0 > LH - 1) y0 = LH - 1;
        int y1 = y0 + 1;  if (y1 > LH - 1) y1 = LH - 1;
        float wy = yf - (float)y0;

        const float2* AB0 = g_AB + ((size_t)img * LH + y0) * LW;
        const float2* AB1 = g_AB + ((size_t)img * LH + y1) * LW;
#pragma unroll
        for (int i = 0; i < 2; ++i) {
            int xc = t + i * UPTHREADS;
            float2 v0 = __ldg(AB0 + xc);
            float2 v1 = __ldg(AB1 + xc);
            sAB[rr][xc] = make_float2(v0.x + wy * (v1.x - v0.x),
                                      v0.y + wy * (v1.y - v0.y));
        }
    }
    __syncthreads();

#pragma unroll
    for (int c = 0; c < 2 * UROWS; ++c) {
        int row  = c >> 1;               // 0..3
        int half = c & 1;                // 0..1
        int xq   = half * 1024 + t * 4;
        size_t off = ((size_t)img * HW + (oyb + row)) * HW + xq;

        float4 hr = __ldcs(reinterpret_cast<const float4*>(hrx + off));
        float hv[4] = {hr.x, hr.y, hr.z, hr.w};
        float res[4];
#pragma unroll
        for (int k = 0; k < 4; ++k) {
            int ox = xq + k;
            float xf = (float)ox * SC;
            int x0 = (int)xf; if (x0 > LW - 1) x0 = LW - 1;
            int x1 = x0 + 1;  if (x1 > LW - 1) x1 = LW - 1;
            float wx = xf - (float)x0;
            float2 p = sAB[row][x0];
            float2 q = sAB[row][x1];
            float Av = p.x + wx * (q.x - p.x);
            float Bv = p.y + wx * (q.y - p.y);
            res[k] = Av * hv[k] + Bv;
        }
        __stcs(reinterpret_cast<float4*>(out + off),
               make_float4(res[0], res[1], res[2], res[3]));
    }
}

// ---------------------------------------------------------------------------
extern "C" void kernel_launch(void* const* d_in, const int* in_sizes, int n_in,
                              void* d_out, int out_size) {
    const float* lrx = (const float*)d_in[0];
    const float* lry = (const float*)d_in[1];
    const float* hrx = (const float*)d_in[2];
    float* out = (float*)d_out;

    dim3 sgrid(LW / TC, LH / TR, NIMG);      // 8 x 32 x 12 = 3072 blocks
    stats_kernel<<<sgrid, STH>>>(lrx, lry);

    upsample_kernel<<<NIMG * (HW / UROWS), UPTHREADS>>>(hrx, out);
}

// round 10
// speedup vs baseline: 1.0406x; 1.0406x over previous
#include <cuda_runtime.h>

#define LW 512
#define LH 512
#define NIMG 12
#define RAD 8
#define HW 2048

// Low-res {A, b} interleaved — only intermediate that touches HBM (24 MB).
__device__ float2 g_AB[(size_t)NIMG * LH * LW];

// ---------------------------------------------------------------------------
// Kernel 1 (fused stats). Round-4 structure, retuned for occupancy:
//   TR 16 -> 8 (shorter serial chain, 2x blocks), ABsh dropped (direct global
//   write), smem 41.7 -> 22.3 KB (~8 blocks/SM instead of 5).
// Tile = 64 out-cols x 8 out-rows. Grid = 8 x 64 x 12 = 6144 blocks, 128 thr.
// FIX vs round 8: prologue row guard now checks rr < LH too (with TR=8 the
// last strip has r0=504, so r0+RAD=512 would read out of bounds).
// ---------------------------------------------------------------------------
#define TC 64                 // out cols per tile
#define TR 8                  // out rows per tile
#define VC (TC + 2 * RAD)     // 80 loaded cols
#define VW 89                 // padded V row width (vpad(79)=88 -> 89)
#define STH 128

__device__ __forceinline__ int vpad(int v) { return v + (v >> 3); }

__global__ __launch_bounds__(STH) void stats_kernel(const float* __restrict__ lrx,
                                                    const float* __restrict__ lry) {
    __shared__ float4 Vsh[TR][VW];              // 11.4 KB vertical window sums
    __shared__ float2 ring[2 * RAD + 1][VC];    // 10.9 KB raw-row ring {x,y}

    int img = blockIdx.z;
    int cb  = blockIdx.x * TC;
    int r0  = blockIdx.y * TR;
    int t   = threadIdx.x;

    const float* xim = lrx + (size_t)img * LH * LW;
    const float* yim = lry + (size_t)img * LH * LW;

    // ---------------- phase 1: vertical sliding windows -------------------
    if (t < VC) {
        int gcol = cb - RAD + t;                // may be <0 or >=LW at edges
        bool cok = (gcol >= 0 && gcol < LW);
        float sx = 0.f, sy = 0.f, sxy = 0.f, sxx = 0.f;

        // init: rows r0-8 .. r0+8 (rows outside [0,LH) contribute zero)
        for (int rr = r0 - RAD; rr <= r0 + RAD; ++rr) {
            float xv = 0.f, yv = 0.f;
            if (cok && rr >= 0 && rr < LH) {
                xv = __ldg(xim + (size_t)rr * LW + gcol);
                yv = __ldg(yim + (size_t)rr * LW + gcol);
            }
            ring[(rr + 17) % 17][t] = make_float2(xv, yv);
            sx += xv; sy += yv; sxy += xv * yv; sxx += xv * xv;
        }

        for (int i = 0; i < TR; ++i) {
            Vsh[i][vpad(t)] = make_float4(sx, sy, sxy, sxx);

            int rsub = r0 + i - RAD;
            int radd = r0 + i + RAD + 1;        // radd - rsub = 17: same slot
            if (rsub >= 0) {
                float2 o = ring[(rsub + 17) % 17][t];  // read old FIRST
                sx -= o.x; sy -= o.y; sxy -= o.x * o.y; sxx -= o.x * o.x;
            }
            float xv = 0.f, yv = 0.f;
            if (cok && radd < LH) {
                xv = __ldg(xim + (size_t)radd * LW + gcol);
                yv = __ldg(yim + (size_t)radd * LW + gcol);
            }
            ring[radd % 17][t] = make_float2(xv, yv);
            sx += xv; sy += yv; sxy += xv * yv; sxx += xv * xv;
        }
    }
    __syncthreads();

    // ---------------- phase 2: horizontal sliding + A,b (direct write) ----
    {
        int i   = t >> 4;          // row in tile, 0..7
        int seg = t & 15;          // 4-px segment, 0..15
        int c0  = seg * 4;
        int r   = r0 + i;

        int ylo = r - RAD; if (ylo < 0) ylo = 0;
        int yhi = r + RAD; if (yhi > LH - 1) yhi = LH - 1;
        float ny = (float)(yhi - ylo + 1);

        float sx = 0.f, sy = 0.f, sxy = 0.f, sxx = 0.f;
#pragma unroll
        for (int v = c0; v <= c0 + 2 * RAD; ++v) {
            float4 w = Vsh[i][vpad(v)];
            sx += w.x; sy += w.y; sxy += w.z; sxx += w.w;
        }

        size_t abase = (size_t)img * LH * LW + (size_t)r * LW;
#pragma unroll
        for (int k = 0; k < 4; ++k) {
            int c  = c0 + k;
            int gc = cb + c;
            int xlo = gc - RAD; if (xlo < 0) xlo = 0;
            int xhi = gc + RAD; if (xhi > LW - 1) xhi = LW - 1;
            float invN = 1.0f / ((float)(xhi - xlo + 1) * ny);

            float mx  = sx  * invN;
            float my  = sy  * invN;
            float cov = sxy * invN - mx * my;
            float var = sxx * invN - mx * mx;
            float A   = cov / (var + 1e-8f);
            g_AB[abase + gc] = make_float2(A, my - A * mx);

            if (k < 3) {
                float4 a = Vsh[i][vpad(c + 2 * RAD + 1)];
                float4 s = Vsh[i][vpad(c)];
                sx += a.x - s.x; sy += a.y - s.y;
                sxy += a.z - s.z; sxx += a.w - s.w;
            }
        }
    }
}

// ---------------------------------------------------------------------------
// Kernel 2: fused bilinear upsample — round-4 version VERBATIM (68.3us,
// 68% DRAM, occ 86%). One block = one output row, 256 thr x 8 px.
// ---------------------------------------------------------------------------
#define UPTHREADS 256

__global__ __launch_bounds__(UPTHREADS) void upsample_kernel(
        const float* __restrict__ hrx, float* __restrict__ out) {
    int bid = blockIdx.x;
    int oy  = bid & 2047;
    int img = bid >> 11;
    int t   = threadIdx.x;

    const float SC = 511.0f / 2047.0f;

    float yf = (float)oy * SC;
    int y0 = (int)yf; if (y0 > LH - 1) y0 = LH - 1;
    int y1 = y0 + 1;  if (y1 > LH - 1) y1 = LH - 1;
    float wy = yf - (float)y0;

    const float2* AB0 = g_AB + ((size_t)img * LH + y0) * LW;
    const float2* AB1 = g_AB + ((size_t)img * LH + y1) * LW;

    __shared__ float2 sAB[LW];   // y-interpolated {A,b} for the whole row

#pragma unroll
    for (int i = 0; i < 2; ++i) {
        int xc = t + i * UPTHREADS;
        float2 v0 = AB0[xc];
        float2 v1 = AB1[xc];
        sAB[xc] = make_float2(v0.x + wy * (v1.x - v0.x),
                              v0.y + wy * (v1.y - v0.y));
    }
    __syncthreads();

    size_t rowoff = ((size_t)img * HW + oy) * HW;

#pragma unroll
    for (int half = 0; half < 2; ++half) {
        int xq = half * 1024 + t * 4;
        size_t off = rowoff + xq;
        float4 hr = __ldcs(reinterpret_cast<const float4*>(hrx + off));
        float hv[4] = {hr.x, hr.y, hr.z, hr.w};
        float res[4];
#pragma unroll
        for (int k = 0; k < 4; ++k) {
            int ox = xq + k;
            float xf = (float)ox * SC;
            int x0 = (int)xf; if (x0 > LW - 1) x0 = LW - 1;
            int x1 = x0 + 1;  if (x1 > LW - 1) x1 = LW - 1;
            float wx = xf - (float)x0;
            float2 p = sAB[x0];
            float2 q = sAB[x1];
            float Av = p.x + wx * (q.x - p.x);
            float Bv = p.y + wx * (q.y - p.y);
            res[k] = Av * hv[k] + Bv;
        }
        __stcs(reinterpret_cast<float4*>(out + off),
               make_float4(res[0], res[1], res[2], res[3]));
    }
}

// ---------------------------------------------------------------------------
extern "C" void kernel_launch(void* const* d_in, const int* in_sizes, int n_in,
                              void* d_out, int out_size) {
    const float* lrx = (const float*)d_in[0];
    const float* lry = (const float*)d_in[1];
    const float* hrx = (const float*)d_in[2];
    float* out = (float*)d_out;

    dim3 sgrid(LW / TC, LH / TR, NIMG);      // 8 x 64 x 12 = 6144 blocks
    stats_kernel<<<sgrid, STH>>>(lrx, lry);

    upsample_kernel<<<NIMG * HW, UPTHREADS>>>(hrx, out);
}

// round 11
// speedup vs baseline: 1.0883x; 1.0458x over previous
#include <cuda_runtime.h>

#define LW 512
#define LH 512
#define NIMG 12
#define RAD 8
#define HW 2048

// Low-res {A, b} interleaved — only intermediate that touches HBM (~25 MB).
__device__ float2 g_AB[(size_t)NIMG * LH * LW];

// ---------------------------------------------------------------------------
// Kernel 1 (fused stats). No shared raw ring: the subtracted row is re-read
// from global (L2-resident input), so all loads are independent of the sum
// chain and can be batched. Vsh-only smem (22.8 KB) at TR=16 -> ~10 blk/SM.
// Tile = 64 out-cols x 16 out-rows. Grid = 8 x 32 x 12 = 3072 blocks, 128 thr.
// ---------------------------------------------------------------------------
#define TC 64                 // out cols per tile
#define TR 16                 // out rows per tile
#define VC (TC + 2 * RAD)     // 80 loaded cols
#define VW 89                 // padded V row width (vpad(79)=88 -> 89)
#define STH 128

__device__ __forceinline__ int vpad(int v) { return v + (v >> 3); }

__global__ __launch_bounds__(STH) void stats_kernel(const float* __restrict__ lrx,
                                                    const float* __restrict__ lry) {
    __shared__ float4 Vsh[TR][VW];              // 22.8 KB vertical window sums

    int img = blockIdx.z;
    int cb  = blockIdx.x * TC;
    int r0  = blockIdx.y * TR;
    int t   = threadIdx.x;

    const float* xim = lrx + (size_t)img * LH * LW;
    const float* yim = lry + (size_t)img * LH * LW;

    // ---------------- phase 1: vertical sliding windows (no ring) ---------
    if (t < VC) {
        int gcol = cb - RAD + t;                // may be <0 or >=LW at edges
        bool cok = (gcol >= 0 && gcol < LW);
        float sx = 0.f, sy = 0.f, sxy = 0.f, sxx = 0.f;

        // init: rows r0-8 .. r0+8 (rows outside [0,LH) contribute zero)
#pragma unroll
        for (int j = 0; j < 2 * RAD + 1; ++j) {
            int rr = r0 - RAD + j;
            float xv = 0.f, yv = 0.f;
            if (cok && rr >= 0 && rr < LH) {
                xv = __ldg(xim + (size_t)rr * LW + gcol);
                yv = __ldg(yim + (size_t)rr * LW + gcol);
            }
            sx += xv; sy += yv; sxy += xv * yv; sxx += xv * xv;
        }

#pragma unroll 4
        for (int i = 0; i < TR; ++i) {
            Vsh[i][vpad(t)] = make_float4(sx, sy, sxy, sxx);

            int rsub = r0 + i - RAD;            // row leaving the window
            int radd = r0 + i + RAD + 1;        // row entering the window
            float ox = 0.f, oy = 0.f;
            if (cok && rsub >= 0) {             // rsub < LH always (<= 503)
                ox = __ldg(xim + (size_t)rsub * LW + gcol);
                oy = __ldg(yim + (size_t)rsub * LW + gcol);
            }
            float xv = 0.f, yv = 0.f;
            if (cok && radd < LH) {
                xv = __ldg(xim + (size_t)radd * LW + gcol);
                yv = __ldg(yim + (size_t)radd * LW + gcol);
            }
            sx  += xv - ox;
            sy  += yv - oy;
            sxy += xv * yv - ox * oy;
            sxx += xv * xv - ox * ox;
        }
    }
    __syncthreads();

    // ---------------- phase 2: horizontal sliding + A,b (direct write) ----
    {
        int i   = t >> 3;          // row in tile, 0..15
        int seg = t & 7;           // 8-px segment, 0..7
        int c0  = seg * 8;
        int r   = r0 + i;

        int ylo = r - RAD; if (ylo < 0) ylo = 0;
        int yhi = r + RAD; if (yhi > LH - 1) yhi = LH - 1;
        float ny = (float)(yhi - ylo + 1);

        float sx = 0.f, sy = 0.f, sxy = 0.f, sxx = 0.f;
#pragma unroll
        for (int v = c0; v <= c0 + 2 * RAD; ++v) {
            float4 w = Vsh[i][vpad(v)];
            sx += w.x; sy += w.y; sxy += w.z; sxx += w.w;
        }

        size_t abase = (size_t)img * LH * LW + (size_t)r * LW;
#pragma unroll
        for (int k = 0; k < 8; ++k) {
            int c  = c0 + k;
            int gc = cb + c;
            int xlo = gc - RAD; if (xlo < 0) xlo = 0;
            int xhi = gc + RAD; if (xhi > LW - 1) xhi = LW - 1;
            float invN = 1.0f / ((float)(xhi - xlo + 1) * ny);

            float mx  = sx  * invN;
            float my  = sy  * invN;
            float cov = sxy * invN - mx * my;
            float var = sxx * invN - mx * mx;
            float A   = cov / (var + 1e-8f);
            g_AB[abase + gc] = make_float2(A, my - A * mx);

            if (k < 7) {
                float4 a = Vsh[i][vpad(c + 2 * RAD + 1)];
                float4 s = Vsh[i][vpad(c)];
                sx += a.x - s.x; sy += a.y - s.y;
                sxy += a.z - s.z; sxx += a.w - s.w;
            }
        }
    }
}

// ---------------------------------------------------------------------------
// Kernel 2: fused bilinear upsample — round-4 version VERBATIM (≈70us,
// 67% DRAM, occ 86%). One block = one output row, 256 thr x 8 px. FROZEN.
// ---------------------------------------------------------------------------
#define UPTHREADS 256

__global__ __launch_bounds__(UPTHREADS) void upsample_kernel(
        const float* __restrict__ hrx, float* __restrict__ out) {
    int bid = blockIdx.x;
    int oy  = bid & 2047;
    int img = bid >> 11;
    int t   = threadIdx.x;

    const float SC = 511.0f / 2047.0f;

    float yf = (float)oy * SC;
    int y0 = (int)yf; if (y0 > LH - 1) y0 = LH - 1;
    int y1 = y0 + 1;  if (y1 > LH - 1) y1 = LH - 1;
    float wy = yf - (float)y0;

    const float2* AB0 = g_AB + ((size_t)img * LH + y0) * LW;
    const float2* AB1 = g_AB + ((size_t)img * LH + y1) * LW;

    __shared__ float2 sAB[LW];   // y-interpolated {A,b} for the whole row

#pragma unroll
    for (int i = 0; i < 2; ++i) {
        int xc = t + i * UPTHREADS;
        float2 v0 = AB0[xc];
        float2 v1 = AB1[xc];
        sAB[xc] = make_float2(v0.x + wy * (v1.x - v0.x),
                              v0.y + wy * (v1.y - v0.y));
    }
    __syncthreads();

    size_t rowoff = ((size_t)img * HW + oy) * HW;

#pragma unroll
    for (int half = 0; half < 2; ++half) {
        int xq = half * 1024 + t * 4;
        size_t off = rowoff + xq;
        float4 hr = __ldcs(reinterpret_cast<const float4*>(hrx + off));
        float hv[4] = {hr.x, hr.y, hr.z, hr.w};
        float res[4];
#pragma unroll
        for (int k = 0; k < 4; ++k) {
            int ox = xq + k;
            float xf = (float)ox * SC;
            int x0 = (int)xf; if (x0 > LW - 1) x0 = LW - 1;
            int x1 = x0 + 1;  if (x1 > LW - 1) x1 = LW - 1;
            float wx = xf - (float)x0;
            float2 p = sAB[x0];
            float2 q = sAB[x1];
            float Av = p.x + wx * (q.x - p.x);
            float Bv = p.y + wx * (q.y - p.y);
            res[k] = Av * hv[k] + Bv;
        }
        __stcs(reinterpret_cast<float4*>(out + off),
               make_float4(res[0], res[1], res[2], res[3]));
    }
}

// ---------------------------------------------------------------------------
extern "C" void kernel_launch(void* const* d_in, const int* in_sizes, int n_in,
                              void* d_out, int out_size) {
    const float* lrx = (const float*)d_in[0];
    const float* lry = (const float*)d_in[1];
    const float* hrx = (const float*)d_in[2];
    float* out = (float*)d_out;

    dim3 sgrid(LW / TC, LH / TR, NIMG);      // 8 x 32 x 12 = 3072 blocks
    stats_kernel<<<sgrid, STH>>>(lrx, lry);

    upsample_kernel<<<NIMG * HW, UPTHREADS>>>(hrx, out);
}

// round 12
// speedup vs baseline: 1.0894x; 1.0010x over previous
#include <cuda_runtime.h>

#define LW 512
#define LH 512
#define NIMG 12
#define RAD 8
#define HW 2048

// Low-res {A, b} interleaved — only intermediate that touches HBM (~25 MB).
__device__ float2 g_AB[(size_t)NIMG * LH * LW];

// ---------------------------------------------------------------------------
// Kernel 1 (fused stats). Phase 1 vertical chain SPLIT into two groups:
//   threads  0- 79: rows 0- 7 of the tile (own prologue + 8 slides)
//   threads 80-159: rows 8-15 of the tile (own prologue + 8 slides)
// Chain 33 -> 25 steps, active phase-1 threads 80 -> 160. Loads come from
// L2-resident input (no ring). Phase 2 unchanged.
// Tile = 64 out-cols x 16 out-rows. Grid = 8 x 32 x 12 = 3072 blocks, 160 thr.
// ---------------------------------------------------------------------------
#define TC 64                 // out cols per tile
#define TR 16                 // out rows per tile
#define VC (TC + 2 * RAD)     // 80 loaded cols
#define VW 89                 // padded V row width (vpad(79)=88 -> 89)
#define STH 160
#define HTR 8                 // rows per chain group

__device__ __forceinline__ int vpad(int v) { return v + (v >> 3); }

__global__ __launch_bounds__(STH) void stats_kernel(const float* __restrict__ lrx,
                                                    const float* __restrict__ lry) {
    __shared__ float4 Vsh[TR][VW];              // 22.8 KB vertical window sums

    int img = blockIdx.z;
    int cb  = blockIdx.x * TC;
    int r0  = blockIdx.y * TR;
    int t   = threadIdx.x;

    const float* xim = lrx + (size_t)img * LH * LW;
    const float* yim = lry + (size_t)img * LH * LW;

    // ---------------- phase 1: two parallel vertical chain groups ---------
    {
        int grp = (t >= VC) ? 1 : 0;            // 0: rows 0-7, 1: rows 8-15
        int tt  = t - grp * VC;                 // 0..79 within group
        int gcol = cb - RAD + tt;               // may be <0 or >=LW at edges
        bool cok = (gcol >= 0 && gcol < LW);
        int rbase = r0 + grp * HTR;             // first output row of group

        float sx = 0.f, sy = 0.f, sxy = 0.f, sxx = 0.f;

        // prologue: rows rbase-8 .. rbase+8 (outside [0,LH) contribute zero;
        // rbase+8 can be 512 at the last strip -> rr<LH guard is load-bearing)
#pragma unroll
        for (int j = 0; j < 2 * RAD + 1; ++j) {
            int rr = rbase - RAD + j;
            float xv = 0.f, yv = 0.f;
            if (cok && rr >= 0 && rr < LH) {
                xv = __ldg(xim + (size_t)rr * LW + gcol);
                yv = __ldg(yim + (size_t)rr * LW + gcol);
            }
            sx += xv; sy += yv; sxy += xv * yv; sxx += xv * xv;
        }

#pragma unroll 4
        for (int i = 0; i < HTR; ++i) {
            Vsh[grp * HTR + i][vpad(tt)] = make_float4(sx, sy, sxy, sxx);

            int rsub = rbase + i - RAD;         // row leaving (max 503 < LH)
            int radd = rbase + i + RAD + 1;     // row entering
            float ox = 0.f, oy = 0.f;
            if (cok && rsub >= 0) {
                ox = __ldg(xim + (size_t)rsub * LW + gcol);
                oy = __ldg(yim + (size_t)rsub * LW + gcol);
            }
            float xv = 0.f, yv = 0.f;
            if (cok && radd < LH) {
                xv = __ldg(xim + (size_t)radd * LW + gcol);
                yv = __ldg(yim + (size_t)radd * LW + gcol);
            }
            sx  += xv - ox;
            sy  += yv - oy;
            sxy += xv * yv - ox * oy;
            sxx += xv * xv - ox * ox;
        }
    }
    __syncthreads();

    // ---------------- phase 2: horizontal sliding + A,b (direct write) ----
    if (t < 128) {
        int i   = t >> 3;          // row in tile, 0..15
        int seg = t & 7;           // 8-px segment, 0..7
        int c0  = seg * 8;
        int r   = r0 + i;

        int ylo = r - RAD; if (ylo < 0) ylo = 0;
        int yhi = r + RAD; if (yhi > LH - 1) yhi = LH - 1;
        float ny = (float)(yhi - ylo + 1);

        float sx = 0.f, sy = 0.f, sxy = 0.f, sxx = 0.f;
#pragma unroll
        for (int v = c0; v <= c0 + 2 * RAD; ++v) {
            float4 w = Vsh[i][vpad(v)];
            sx += w.x; sy += w.y; sxy += w.z; sxx += w.w;
        }

        size_t abase = (size_t)img * LH * LW + (size_t)r * LW;
#pragma unroll
        for (int k = 0; k < 8; ++k) {
            int c  = c0 + k;
            int gc = cb + c;
            int xlo = gc - RAD; if (xlo < 0) xlo = 0;
            int xhi = gc + RAD; if (xhi > LW - 1) xhi = LW - 1;
            float invN = 1.0f / ((float)(xhi - xlo + 1) * ny);

            float mx  = sx  * invN;
            float my  = sy  * invN;
            float cov = sxy * invN - mx * my;
            float var = sxx * invN - mx * mx;
            float A   = cov / (var + 1e-8f);
            g_AB[abase + gc] = make_float2(A, my - A * mx);

            if (k < 7) {
                float4 a = Vsh[i][vpad(c + 2 * RAD + 1)];
                float4 s = Vsh[i][vpad(c)];
                sx += a.x - s.x; sy += a.y - s.y;
                sxy += a.z - s.z; sxx += a.w - s.w;
            }
        }
    }
}

// ---------------------------------------------------------------------------
// Kernel 2: fused bilinear upsample — round-4 version VERBATIM (≈70us,
// 67% DRAM, occ 86%). One block = one output row, 256 thr x 8 px. FROZEN.
// ---------------------------------------------------------------------------
#define UPTHREADS 256

__global__ __launch_bounds__(UPTHREADS) void upsample_kernel(
        const float* __restrict__ hrx, float* __restrict__ out) {
    int bid = blockIdx.x;
    int oy  = bid & 2047;
    int img = bid >> 11;
    int t   = threadIdx.x;

    const float SC = 511.0f / 2047.0f;

    float yf = (float)oy * SC;
    int y0 = (int)yf; if (y0 > LH - 1) y0 = LH - 1;
    int y1 = y0 + 1;  if (y1 > LH - 1) y1 = LH - 1;
    float wy = yf - (float)y0;

    const float2* AB0 = g_AB + ((size_t)img * LH + y0) * LW;
    const float2* AB1 = g_AB + ((size_t)img * LH + y1) * LW;

    __shared__ float2 sAB[LW];   // y-interpolated {A,b} for the whole row

#pragma unroll
    for (int i = 0; i < 2; ++i) {
        int xc = t + i * UPTHREADS;
        float2 v0 = AB0[xc];
        float2 v1 = AB1[xc];
        sAB[xc] = make_float2(v0.x + wy * (v1.x - v0.x),
                              v0.y + wy * (v1.y - v0.y));
    }
    __syncthreads();

    size_t rowoff = ((size_t)img * HW + oy) * HW;

#pragma unroll
    for (int half = 0; half < 2; ++half) {
        int xq = half * 1024 + t * 4;
        size_t off = rowoff + xq;
        float4 hr = __ldcs(reinterpret_cast<const float4*>(hrx + off));
        float hv[4] = {hr.x, hr.y, hr.z, hr.w};
        float res[4];
#pragma unroll
        for (int k = 0; k < 4; ++k) {
            int ox = xq + k;
            float xf = (float)ox * SC;
            int x0 = (int)xf; if (x0 > LW - 1) x0 = LW - 1;
            int x1 = x0 + 1;  if (x1 > LW - 1) x1 = LW - 1;
            float wx = xf - (float)x0;
            float2 p = sAB[x0];
            float2 q = sAB[x1];
            float Av = p.x + wx * (q.x - p.x);
            float Bv = p.y + wx * (q.y - p.y);
            res[k] = Av * hv[k] + Bv;
        }
        __stcs(reinterpret_cast<float4*>(out + off),
               make_float4(res[0], res[1], res[2], res[3]));
    }
}

// ---------------------------------------------------------------------------
extern "C" void kernel_launch(void* const* d_in, const int* in_sizes, int n_in,
                              void* d_out, int out_size) {
    const float* lrx = (const float*)d_in[0];
    const float* lry = (const float*)d_in[1];
    const float* hrx = (const float*)d_in[2];
    float* out = (float*)d_out;

    dim3 sgrid(LW / TC, LH / TR, NIMG);      // 8 x 32 x 12 = 3072 blocks
    stats_kernel<<<sgrid, STH>>>(lrx, lry);

    upsample_kernel<<<NIMG * HW, UPTHREADS>>>(hrx, out);
}

// round 14
// speedup vs baseline: 1.0945x; 1.0047x over previous
#include <cuda_runtime.h>

#define LW 512
#define LH 512
#define NIMG 12
#define RAD 8
#define HW 2048

// Low-res {A, b} interleaved — only intermediate that touches HBM (~25 MB).
__device__ float2 g_AB[(size_t)NIMG * LH * LW];

// ---------------------------------------------------------------------------
// Kernel 1 (fused stats) — R12 version VERBATIM (passed, ~27.5us).
// ---------------------------------------------------------------------------
#define TC 64                 // out cols per tile
#define TR 16                 // out rows per tile
#define VC (TC + 2 * RAD)     // 80 loaded cols
#define VW 89                 // padded V row width (vpad(79)=88 -> 89)
#define STH 160
#define HTR 8                 // rows per chain group

__device__ __forceinline__ int vpad(int v) { return v + (v >> 3); }

__global__ __launch_bounds__(STH) void stats_kernel(const float* __restrict__ lrx,
                                                    const float* __restrict__ lry) {
    __shared__ float4 Vsh[TR][VW];              // 22.8 KB vertical window sums

    int img = blockIdx.z;
    int cb  = blockIdx.x * TC;
    int r0  = blockIdx.y * TR;
    int t   = threadIdx.x;

    const float* xim = lrx + (size_t)img * LH * LW;
    const float* yim = lry + (size_t)img * LH * LW;

    // ---------------- phase 1: two parallel vertical chain groups ---------
    {
        int grp = (t >= VC) ? 1 : 0;            // 0: rows 0-7, 1: rows 8-15
        int tt  = t - grp * VC;                 // 0..79 within group
        int gcol = cb - RAD + tt;               // may be <0 or >=LW at edges
        bool cok = (gcol >= 0 && gcol < LW);
        int rbase = r0 + grp * HTR;             // first output row of group

        float sx = 0.f, sy = 0.f, sxy = 0.f, sxx = 0.f;

#pragma unroll
        for (int j = 0; j < 2 * RAD + 1; ++j) {
            int rr = rbase - RAD + j;
            float xv = 0.f, yv = 0.f;
            if (cok && rr >= 0 && rr < LH) {
                xv = __ldg(xim + (size_t)rr * LW + gcol);
                yv = __ldg(yim + (size_t)rr * LW + gcol);
            }
            sx += xv; sy += yv; sxy += xv * yv; sxx += xv * xv;
        }

#pragma unroll 4
        for (int i = 0; i < HTR; ++i) {
            Vsh[grp * HTR + i][vpad(tt)] = make_float4(sx, sy, sxy, sxx);

            int rsub = rbase + i - RAD;         // row leaving (max 503 < LH)
            int radd = rbase + i + RAD + 1;     // row entering
            float ox = 0.f, oy = 0.f;
            if (cok && rsub >= 0) {
                ox = __ldg(xim + (size_t)rsub * LW + gcol);
                oy = __ldg(yim + (size_t)rsub * LW + gcol);
            }
            float xv = 0.f, yv = 0.f;
            if (cok && radd < LH) {
                xv = __ldg(xim + (size_t)radd * LW + gcol);
                yv = __ldg(yim + (size_t)radd * LW + gcol);
            }
            sx  += xv - ox;
            sy  += yv - oy;
            sxy += xv * yv - ox * oy;
            sxx += xv * xv - ox * ox;
        }
    }
    __syncthreads();

    // ---------------- phase 2: horizontal sliding + A,b (direct write) ----
    if (t < 128) {
        int i   = t >> 3;          // row in tile, 0..15
        int seg = t & 7;           // 8-px segment, 0..7
        int c0  = seg * 8;
        int r   = r0 + i;

        int ylo = r - RAD; if (ylo < 0) ylo = 0;
        int yhi = r + RAD; if (yhi > LH - 1) yhi = LH - 1;
        float ny = (float)(yhi - ylo + 1);

        float sx = 0.f, sy = 0.f, sxy = 0.f, sxx = 0.f;
#pragma unroll
        for (int v = c0; v <= c0 + 2 * RAD; ++v) {
            float4 w = Vsh[i][vpad(v)];
            sx += w.x; sy += w.y; sxy += w.z; sxx += w.w;
        }

        size_t abase = (size_t)img * LH * LW + (size_t)r * LW;
#pragma unroll
        for (int k = 0; k < 8; ++k) {
            int c  = c0 + k;
            int gc = cb + c;
            int xlo = gc - RAD; if (xlo < 0) xlo = 0;
            int xhi = gc + RAD; if (xhi > LW - 1) xhi = LW - 1;
            float invN = 1.0f / ((float)(xhi - xlo + 1) * ny);

            float mx  = sx  * invN;
            float my  = sy  * invN;
            float cov = sxy * invN - mx * my;
            float var = sxx * invN - mx * mx;
            float A   = cov / (var + 1e-8f);
            g_AB[abase + gc] = make_float2(A, my - A * mx);

            if (k < 7) {
                float4 a = Vsh[i][vpad(c + 2 * RAD + 1)];
                float4 s = Vsh[i][vpad(c)];
                sx += a.x - s.x; sy += a.y - s.y;
                sxy += a.z - s.z; sxx += a.w - s.w;
            }
        }
    }
}

// ---------------------------------------------------------------------------
// Kernel 2: fused bilinear upsample. Round-4 shell; inner gather reduced
// from 16 LDS.64 (128B) to 6 LDS.64 (48B) per thread: each float4 group of
// 4 px spans at most 2 low-res cells -> load cells xb,xb+1,xb+2 once and
// select per-pixel (one-level predicated selects, ~7 ALU/px).
// ---------------------------------------------------------------------------
#define UPTHREADS 256

__global__ __launch_bounds__(UPTHREADS) void upsample_kernel(
        const float* __restrict__ hrx, float* __restrict__ out) {
    int bid = blockIdx.x;
    int oy  = bid & 2047;
    int img = bid >> 11;
    int t   = threadIdx.x;

    const float SC = 511.0f / 2047.0f;

    float yf = (float)oy * SC;
    int y0 = (int)yf; if (y0 > LH - 1) y0 = LH - 1;
    int y1 = y0 + 1;  if (y1 > LH - 1) y1 = LH - 1;
    float wy = yf - (float)y0;

    const float2* AB0 = g_AB + ((size_t)img * LH + y0) * LW;
    const float2* AB1 = g_AB + ((size_t)img * LH + y1) * LW;

    __shared__ float2 sAB[LW + 1];   // y-interp {A,b}; entry 512 = dup of 511

#pragma unroll
    for (int i = 0; i < 2; ++i) {
        int xc = t + i * UPTHREADS;
        float2 v0 = AB0[xc];
        float2 v1 = AB1[xc];
        sAB[xc] = make_float2(v0.x + wy * (v1.x - v0.x),
                              v0.y + wy * (v1.y - v0.y));
    }
    if (t == 0) {
        float2 v0 = AB0[LW - 1];
        float2 v1 = AB1[LW - 1];
        sAB[LW] = make_float2(v0.x + wy * (v1.x - v0.x),
                              v0.y + wy * (v1.y - v0.y));
    }
    __syncthreads();

    size_t rowoff = ((size_t)img * HW + oy) * HW;

#pragma unroll
    for (int half = 0; half < 2; ++half) {
        int xq = half * 1024 + t * 4;          // first pixel of the float4
        size_t off = rowoff + xq;
        float4 hr = __ldcs(reinterpret_cast<const float4*>(hrx + off));
        float hv[4] = {hr.x, hr.y, hr.z, hr.w};

        float f0 = (float)xq * SC;
        int xb = (int)f0;                      // <= 510 (xq <= 2044)
        float fb = (float)xb;
        float2 p0 = sAB[xb];
        float2 p1 = sAB[xb + 1];
        float2 p2 = sAB[xb + 2];               // <= 512: padded entry

        float res[4];
#pragma unroll
        for (int k = 0; k < 4; ++k) {
            float f = (float)(xq + k) * SC;
            bool c = (f - fb) >= 1.0f;         // x0 == xb+1 ?
            float wx = f - (c ? fb + 1.0f : fb);
            float pA = c ? p1.x : p0.x;
            float pB = c ? p1.y : p0.y;
            float qA = c ? p2.x : p1.x;
            float qB = c ? p2.y : p1.y;
            float Av = pA + wx * (qA - pA);
            float Bv = pB + wx * (qB - pB);
            res[k] = Av * hv[k] + Bv;
        }

        __stcs(reinterpret_cast<float4*>(out + off),
               make_float4(res[0], res[1], res[2], res[3]));
    }
}

// ---------------------------------------------------------------------------
extern "C" void kernel_launch(void* const* d_in, const int* in_sizes, int n_in,
                              void* d_out, int out_size) {
    const float* lrx = (const float*)d_in[0];
    const float* lry = (const float*)d_in[1];
    const float* hrx = (const float*)d_in[2];
    float* out = (float*)d_out;

    dim3 sgrid(LW / TC, LH / TR, NIMG);      // 8 x 32 x 12 = 3072 blocks
    stats_kernel<<<sgrid, STH>>>(lrx, lry);

    upsample_kernel<<<NIMG * HW, UPTHREADS>>>(hrx, out);
}

// round 15
// speedup vs baseline: 1.1846x; 1.0824x over previous
#include <cuda_runtime.h>

#define LW 512
#define LH 512
#define NIMG 12
#define RAD 8
#define HW 2048

// Low-res {A, b} interleaved — only intermediate that touches HBM (~25 MB).
__device__ float2 g_AB[(size_t)NIMG * LH * LW];

// ---------------------------------------------------------------------------
// Kernel 1 (fused stats) — R12 version VERBATIM (passed, ~26-28us plateau).
// ---------------------------------------------------------------------------
#define TC 64                 // out cols per tile
#define TR 16                 // out rows per tile
#define VC (TC + 2 * RAD)     // 80 loaded cols
#define VW 89                 // padded V row width (vpad(79)=88 -> 89)
#define STH 160
#define HTR 8                 // rows per chain group

__device__ __forceinline__ int vpad(int v) { return v + (v >> 3); }

__global__ __launch_bounds__(STH) void stats_kernel(const float* __restrict__ lrx,
                                                    const float* __restrict__ lry) {
    __shared__ float4 Vsh[TR][VW];              // 22.8 KB vertical window sums

    int img = blockIdx.z;
    int cb  = blockIdx.x * TC;
    int r0  = blockIdx.y * TR;
    int t   = threadIdx.x;

    const float* xim = lrx + (size_t)img * LH * LW;
    const float* yim = lry + (size_t)img * LH * LW;

    // ---------------- phase 1: two parallel vertical chain groups ---------
    {
        int grp = (t >= VC) ? 1 : 0;            // 0: rows 0-7, 1: rows 8-15
        int tt  = t - grp * VC;                 // 0..79 within group
        int gcol = cb - RAD + tt;               // may be <0 or >=LW at edges
        bool cok = (gcol >= 0 && gcol < LW);
        int rbase = r0 + grp * HTR;             // first output row of group

        float sx = 0.f, sy = 0.f, sxy = 0.f, sxx = 0.f;

#pragma unroll
        for (int j = 0; j < 2 * RAD + 1; ++j) {
            int rr = rbase - RAD + j;
            float xv = 0.f, yv = 0.f;
            if (cok && rr >= 0 && rr < LH) {
                xv = __ldg(xim + (size_t)rr * LW + gcol);
                yv = __ldg(yim + (size_t)rr * LW + gcol);
            }
            sx += xv; sy += yv; sxy += xv * yv; sxx += xv * xv;
        }

#pragma unroll 4
        for (int i = 0; i < HTR; ++i) {
            Vsh[grp * HTR + i][vpad(tt)] = make_float4(sx, sy, sxy, sxx);

            int rsub = rbase + i - RAD;         // row leaving (max 503 < LH)
            int radd = rbase + i + RAD + 1;     // row entering
            float ox = 0.f, oy = 0.f;
            if (cok && rsub >= 0) {
                ox = __ldg(xim + (size_t)rsub * LW + gcol);
                oy = __ldg(yim + (size_t)rsub * LW + gcol);
            }
            float xv = 0.f, yv = 0.f;
            if (cok && radd < LH) {
                xv = __ldg(xim + (size_t)radd * LW + gcol);
                yv = __ldg(yim + (size_t)radd * LW + gcol);
            }
            sx  += xv - ox;
            sy  += yv - oy;
            sxy += xv * yv - ox * oy;
            sxx += xv * xv - ox * ox;
        }
    }
    __syncthreads();

    // ---------------- phase 2: horizontal sliding + A,b (direct write) ----
    if (t < 128) {
        int i   = t >> 3;          // row in tile, 0..15
        int seg = t & 7;           // 8-px segment, 0..7
        int c0  = seg * 8;
        int r   = r0 + i;

        int ylo = r - RAD; if (ylo < 0) ylo = 0;
        int yhi = r + RAD; if (yhi > LH - 1) yhi = LH - 1;
        float ny = (float)(yhi - ylo + 1);

        float sx = 0.f, sy = 0.f, sxy = 0.f, sxx = 0.f;
#pragma unroll
        for (int v = c0; v <= c0 + 2 * RAD; ++v) {
            float4 w = Vsh[i][vpad(v)];
            sx += w.x; sy += w.y; sxy += w.z; sxx += w.w;
        }

        size_t abase = (size_t)img * LH * LW + (size_t)r * LW;
#pragma unroll
        for (int k = 0; k < 8; ++k) {
            int c  = c0 + k;
            int gc = cb + c;
            int xlo = gc - RAD; if (xlo < 0) xlo = 0;
            int xhi = gc + RAD; if (xhi > LW - 1) xhi = LW - 1;
            float invN = 1.0f / ((float)(xhi - xlo + 1) * ny);

            float mx  = sx  * invN;
            float my  = sy  * invN;
            float cov = sxy * invN - mx * my;
            float var = sxx * invN - mx * mx;
            float A   = cov / (var + 1e-8f);
            g_AB[abase + gc] = make_float2(A, my - A * mx);

            if (k < 7) {
                float4 a = Vsh[i][vpad(c + 2 * RAD + 1)];
                float4 s = Vsh[i][vpad(c)];
                sx += a.x - s.x; sy += a.y - s.y;
                sxy += a.z - s.z; sxx += a.w - s.w;
            }
        }
    }
}

// ---------------------------------------------------------------------------
// Kernel 2: fused bilinear upsample. Same math as R14, but BOTH hr_x float4
// loads are issued at the very top of the kernel — before the sAB fill and
// __syncthreads() — so each warp holds 256B of DRAM reads in flight through
// the whole setup phase (latency-bound -> more bytes in flight).
// ---------------------------------------------------------------------------
#define UPTHREADS 256

__global__ __launch_bounds__(UPTHREADS) void upsample_kernel(
        const float* __restrict__ hrx, float* __restrict__ out) {
    int bid = blockIdx.x;
    int oy  = bid & 2047;
    int img = bid >> 11;
    int t   = threadIdx.x;

    const float SC = 511.0f / 2047.0f;

    // ---- issue the two streaming reads FIRST (independent of shared) ----
    size_t rowoff = ((size_t)img * HW + oy) * HW;
    int xq0 = t * 4;
    int xq1 = 1024 + t * 4;
    float4 h0 = __ldcs(reinterpret_cast<const float4*>(hrx + rowoff + xq0));
    float4 h1 = __ldcs(reinterpret_cast<const float4*>(hrx + rowoff + xq1));

    // ---- y-interpolation setup ----
    float yf = (float)oy * SC;
    int y0 = (int)yf; if (y0 > LH - 1) y0 = LH - 1;
    int y1 = y0 + 1;  if (y1 > LH - 1) y1 = LH - 1;
    float wy = yf - (float)y0;

    const float2* AB0 = g_AB + ((size_t)img * LH + y0) * LW;
    const float2* AB1 = g_AB + ((size_t)img * LH + y1) * LW;

    __shared__ float2 sAB[LW + 1];   // y-interp {A,b}; entry 512 = dup of 511

#pragma unroll
    for (int i = 0; i < 2; ++i) {
        int xc = t + i * UPTHREADS;
        float2 v0 = AB0[xc];
        float2 v1 = AB1[xc];
        sAB[xc] = make_float2(v0.x + wy * (v1.x - v0.x),
                              v0.y + wy * (v1.y - v0.y));
    }
    if (t == 0) {
        float2 v0 = AB0[LW - 1];
        float2 v1 = AB1[LW - 1];
        sAB[LW] = make_float2(v0.x + wy * (v1.x - v0.x),
                              v0.y + wy * (v1.y - v0.y));
    }
    __syncthreads();

#pragma unroll
    for (int half = 0; half < 2; ++half) {
        int xq = half ? xq1 : xq0;
        float4 hr = half ? h1 : h0;
        float hv[4] = {hr.x, hr.y, hr.z, hr.w};

        float f0 = (float)xq * SC;
        int xb = (int)f0;                      // <= 510 (xq <= 2044)
        float fb = (float)xb;
        float2 p0 = sAB[xb];
        float2 p1 = sAB[xb + 1];
        float2 p2 = sAB[xb + 2];               // <= 512: padded entry

        float res[4];
#pragma unroll
        for (int k = 0; k < 4; ++k) {
            float f = (float)(xq + k) * SC;
            bool c = (f - fb) >= 1.0f;         // x0 == xb+1 ?
            float wx = f - (c ? fb + 1.0f : fb);
            float pA = c ? p1.x : p0.x;
            float pB = c ? p1.y : p0.y;
            float qA = c ? p2.x : p1.x;
            float qB = c ? p2.y : p1.y;
            float Av = pA + wx * (qA - pA);
            float Bv = pB + wx * (qB - pB);
            res[k] = Av * hv[k] + Bv;
        }

        __stcs(reinterpret_cast<float4*>(out + rowoff + xq),
               make_float4(res[0], res[1], res[2], res[3]));
    }
}

// ---------------------------------------------------------------------------
extern "C" void kernel_launch(void* const* d_in, const int* in_sizes, int n_in,
                              void* d_out, int out_size) {
    const float* lrx = (const float*)d_in[0];
    const float* lry = (const float*)d_in[1];
    const float* hrx = (const float*)d_in[2];
    float* out = (float*)d_out;

    dim3 sgrid(LW / TC, LH / TR, NIMG);      // 8 x 32 x 12 = 3072 blocks
    stats_kernel<<<sgrid, STH>>>(lrx, lry);

    upsample_kernel<<<NIMG * HW, UPTHREADS>>>(hrx, out);
}